// round 3
// baseline (speedup 1.0000x reference)
#include <cuda_runtime.h>
#include <cuda_fp16.h>
#include <cstdint>

// Problem constants
constexpr int BATCH = 64;
constexpr int IN    = 8192;
constexpr int OUT   = 8192;

// Tiling
constexpr int KC  = 64;             // K chunk
constexpr int TO  = 64;             // OUT tile per block
constexpr int NCH = IN / KC;        // 128 k-chunks
constexpr int THREADS = 256;
constexpr int STAGES  = 3;

constexpr int XSH = 72;             // x smem stride in halves  (conflict-free mma reads)
constexpr int XSF = 68;             // x smem stride in floats  (mild 2-way on lds.64, acceptable)

// smem layout (dynamic)
constexpr int QW_STAGE_INTS  = TO * KC;                       // 4096 ints = 16 KB
constexpr int X_STAGE_FLOATS = TO * XSF;                      // 4352 floats = 17408 B (f16 path fits inside)
constexpr int SMEM_QW_OFF    = 0;
constexpr int SMEM_QW_BYTES  = STAGES * QW_STAGE_INTS * 4;    // 49152
constexpr int SMEM_X_OFF     = SMEM_QW_OFF + SMEM_QW_BYTES;
constexpr int SMEM_X_BYTES   = STAGES * X_STAGE_FLOATS * 4;   // 52224
constexpr int SMEM_W_OFF     = SMEM_X_OFF + SMEM_X_BYTES;
constexpr int SMEM_W_BYTES   = TO * XSH * 2;                  // 9216
constexpr int SMEM_LUT_OFF   = SMEM_W_OFF + SMEM_W_BYTES;
constexpr int SMEM_LUT_BYTES = TO * 16 * 2;                   // 2048
constexpr int SMEM_TOTAL     = SMEM_LUT_OFF + SMEM_LUT_BYTES; // 112640 B

__device__ int g_is_f32;   // dtype flag written by probe kernel

__device__ __forceinline__ void cp_async16(void* smem_dst, const void* gmem_src) {
    unsigned s = (unsigned)__cvta_generic_to_shared(smem_dst);
    asm volatile("cp.async.cg.shared.global [%0], [%1], 16;\n" :: "r"(s), "l"(gmem_src));
}
__device__ __forceinline__ void cp_commit() {
    asm volatile("cp.async.commit_group;\n" ::: "memory");
}
template <int N>
__device__ __forceinline__ void cp_wait() {
    asm volatile("cp.async.wait_group %0;\n" :: "n"(N) : "memory");
}

__device__ __forceinline__ void mma_m16n8k16(float& c0, float& c1, float& c2, float& c3,
                                             unsigned a0, unsigned a1, unsigned a2, unsigned a3,
                                             unsigned b0, unsigned b1) {
    asm volatile(
        "mma.sync.aligned.m16n8k16.row.col.f32.f16.f16.f32 "
        "{%0,%1,%2,%3}, {%4,%5,%6,%7}, {%8,%9}, {%0,%1,%2,%3};\n"
        : "+f"(c0), "+f"(c1), "+f"(c2), "+f"(c3)
        : "r"(a0), "r"(a1), "r"(a2), "r"(a3), "r"(b0), "r"(b1));
}

// ---------------------------------------------------------------------------
// Probe: decide whether the fp16 reference arrays were stored as float32 or
// half. Reads the first 64 words of lut. As f32, N(0,0.05) samples have |v|
// in (1e-4, 1) with prob ~0.998 per word. As packed half pairs, the f32
// interpretation's exponent byte comes from a half's sign/exponent bits ->
// |v| < ~3e-5 essentially always. Majority vote over 64 words.
// ---------------------------------------------------------------------------
__global__ void probe_kernel(const unsigned* __restrict__ lut_words) {
    if (threadIdx.x == 0) {
        int c = 0;
#pragma unroll 1
        for (int i = 0; i < 64; i++) {
            float a = fabsf(__uint_as_float(lut_words[i]));
            if (a > 1e-4f && a < 1.0f) c++;
        }
        g_is_f32 = (c >= 32) ? 1 : 0;
    }
}

template <bool F32>
__device__ __forceinline__ void run_impl(const void* __restrict__ xp,
                                         const int*  __restrict__ qw,
                                         const void* __restrict__ lutp,
                                         void*       __restrict__ outp,
                                         char* smem) {
    int*    qw_s   = reinterpret_cast<int*>(smem + SMEM_QW_OFF);
    char*   x_base = smem + SMEM_X_OFF;
    __half* w_s    = reinterpret_cast<__half*>(smem + SMEM_W_OFF);
    __half* lut_s  = reinterpret_cast<__half*>(smem + SMEM_LUT_OFF);

    const int tid  = threadIdx.x;
    const int lane = tid & 31;
    const int wid  = tid >> 5;
    const int rblk = blockIdx.x * TO;

    // ---- load this CTA's 64 LUT rows into smem (as half) ----
    if (F32) {
        const float* lf = reinterpret_cast<const float*>(lutp);
        for (int i = tid; i < TO * 16; i += THREADS)
            lut_s[i] = __float2half_rn(lf[(size_t)rblk * 16 + i]);
    } else {
        const __half* lh = reinterpret_cast<const __half*>(lutp);
        for (int i = tid; i < TO * 16; i += THREADS)
            lut_s[i] = lh[(size_t)rblk * 16 + i];
    }

    // ---- cp.async tile mapping ----
    const int pr = tid >> 2;   // row within tile (0..63)
    const int ps = tid & 3;    // segment id

    auto prefetch = [&](int c, int buf) {
        const int k0 = c * KC;
        if (F32) {
            const float* xg = reinterpret_cast<const float*>(xp) + (size_t)pr * IN + k0;
            float* xd = reinterpret_cast<float*>(x_base + buf * (X_STAGE_FLOATS * 4)) + pr * XSF;
#pragma unroll
            for (int i = 0; i < 4; i++)
                cp_async16(xd + (ps + 4 * i) * 4, xg + (ps + 4 * i) * 4);
        } else {
            const __half* xg = reinterpret_cast<const __half*>(xp) + (size_t)pr * IN + k0;
            __half* xd = reinterpret_cast<__half*>(x_base + buf * (X_STAGE_FLOATS * 4)) + pr * XSH;
            cp_async16(xd + ps * 8,       xg + ps * 8);
            cp_async16(xd + (ps + 4) * 8, xg + (ps + 4) * 8);
        }
        // qweight tile: rows rblk+pr
        const int* qg = qw + (size_t)(rblk + pr) * IN + k0;
        int* qd = qw_s + buf * QW_STAGE_INTS + pr * KC;
#pragma unroll
        for (int i = 0; i < 4; i++)
            cp_async16(qd + (ps + 4 * i) * 4, qg + (ps + 4 * i) * 4);
    };

    prefetch(0, 0); cp_commit();
    prefetch(1, 1); cp_commit();

    // mma warp tiling: warp computes [16 m][32 n]
    const int m0 = (wid & 3) * 16;
    const int n0 = (wid >> 2) * 32;
    const int g  = lane >> 2;
    const int t  = lane & 3;

    // a-fragment loader (converts f32 smem -> packed half2 when needed)
    auto lda = [&](const char* xb, int row, int kk) -> unsigned {
        if (F32) {
            const float* p = reinterpret_cast<const float*>(xb) + row * XSF + kk;
            float2 v = *reinterpret_cast<const float2*>(p);
            __half2 h = __floats2half2_rn(v.x, v.y);
            return *reinterpret_cast<unsigned*>(&h);
        } else {
            return *reinterpret_cast<const unsigned*>(
                reinterpret_cast<const __half*>(xb) + row * XSH + kk);
        }
    };

    float acc[4][4];
#pragma unroll
    for (int j = 0; j < 4; j++)
#pragma unroll
        for (int r = 0; r < 4; r++) acc[j][r] = 0.0f;

    for (int c = 0; c < NCH; c++) {
        const int buf = c % STAGES;
        if (c + 2 < NCH) {
            prefetch(c + 2, (c + 2) % STAGES);
            cp_commit();
            cp_wait<2>();
        } else if (c + 1 < NCH) {
            cp_wait<1>();
        } else {
            cp_wait<0>();
        }
        __syncthreads();   // chunk c staged; also orders lut_s on first iter

        // ---- dequant qw_s[buf] -> w_s (fp16); warp owns 8 rows ----
        const int* qb = qw_s + buf * QW_STAGE_INTS;
#pragma unroll
        for (int i = 0; i < 8; i++) {
            const int row = wid * 8 + i;
            const __half* lrow = lut_s + row * 16;   // 32B row; random-index LDS
            int2 v = *reinterpret_cast<const int2*>(qb + row * KC + lane * 2);
            __half2 hh = __halves2half2(lrow[v.x & 15], lrow[v.y & 15]);
            *reinterpret_cast<__half2*>(w_s + row * XSH + lane * 2) = hh;
        }
        __syncthreads();

        // ---- mma over this k-chunk (4 k-steps of 16) ----
        const char* xb = x_base + buf * (X_STAGE_FLOATS * 4);
#pragma unroll
        for (int ks = 0; ks < 4; ks++) {
            const int k = ks * 16;
            unsigned a0 = lda(xb, m0 + g,     k + t * 2);
            unsigned a1 = lda(xb, m0 + g + 8, k + t * 2);
            unsigned a2 = lda(xb, m0 + g,     k + 8 + t * 2);
            unsigned a3 = lda(xb, m0 + g + 8, k + 8 + t * 2);
#pragma unroll
            for (int j = 0; j < 4; j++) {
                const __half* wr = w_s + (n0 + j * 8 + g) * XSH + k;
                unsigned b0 = *reinterpret_cast<const unsigned*>(wr + t * 2);
                unsigned b1 = *reinterpret_cast<const unsigned*>(wr + 8 + t * 2);
                mma_m16n8k16(acc[j][0], acc[j][1], acc[j][2], acc[j][3],
                             a0, a1, a2, a3, b0, b1);
            }
        }
        __syncthreads();
    }

    // ---- epilogue (round through fp16 to match the fp16 reference matmul) ----
#pragma unroll
    for (int j = 0; j < 4; j++) {
        const int n = rblk + n0 + j * 8 + t * 2;
        if (F32) {
            float* out = reinterpret_cast<float*>(outp);
            float r0 = __half2float(__float2half_rn(acc[j][0]));
            float r1 = __half2float(__float2half_rn(acc[j][1]));
            float r2 = __half2float(__float2half_rn(acc[j][2]));
            float r3 = __half2float(__float2half_rn(acc[j][3]));
            *reinterpret_cast<float2*>(out + (size_t)(m0 + g)     * OUT + n) = make_float2(r0, r1);
            *reinterpret_cast<float2*>(out + (size_t)(m0 + g + 8) * OUT + n) = make_float2(r2, r3);
        } else {
            __half* out = reinterpret_cast<__half*>(outp);
            __half2 lo = __floats2half2_rn(acc[j][0], acc[j][1]);
            __half2 hi = __floats2half2_rn(acc[j][2], acc[j][3]);
            *reinterpret_cast<__half2*>(out + (size_t)(m0 + g)     * OUT + n) = lo;
            *reinterpret_cast<__half2*>(out + (size_t)(m0 + g + 8) * OUT + n) = hi;
        }
    }
}

__global__ __launch_bounds__(THREADS, 1)
void anyprec_linear_kernel(const void* __restrict__ x,
                           const int*  __restrict__ qw,
                           const void* __restrict__ lut,
                           void*       __restrict__ out) {
    extern __shared__ char smem[];
    if (g_is_f32) run_impl<true>(x, qw, lut, out, smem);
    else          run_impl<false>(x, qw, lut, out, smem);
}

extern "C" void kernel_launch(void* const* d_in, const int* in_sizes, int n_in,
                              void* d_out, int out_size) {
    // Identify inputs by element count (robust to ordering):
    //   x: 64*8192 = 524288, qweight: 8192*8192 = 67108864, lut: 8192*16 = 131072
    const void* x = nullptr; const int* qw = nullptr; const void* lut = nullptr;
    for (int i = 0; i < n_in; i++) {
        if (in_sizes[i] == BATCH * IN)      x   = d_in[i];
        else if (in_sizes[i] == OUT * IN)   qw  = (const int*)d_in[i];
        else if (in_sizes[i] == OUT * 16)   lut = d_in[i];
    }

    // Idempotent, runs every call (no static guards per harness rules).
    cudaFuncSetAttribute(anyprec_linear_kernel,
                         cudaFuncAttributeMaxDynamicSharedMemorySize, SMEM_TOTAL);

    probe_kernel<<<1, 32>>>(reinterpret_cast<const unsigned*>(lut));
    anyprec_linear_kernel<<<OUT / TO, THREADS, SMEM_TOTAL>>>(x, qw, lut, d_out);
}

// round 5
// speedup vs baseline: 1.6303x; 1.6303x over previous
#include <cuda_runtime.h>
#include <cuda_fp16.h>
#include <cstdint>

// Problem constants
constexpr int BATCH = 64;
constexpr int IN    = 8192;
constexpr int OUT   = 8192;

// Tiling
constexpr int KC  = 64;              // K chunk
constexpr int TO  = 64;              // OUT tile per block
constexpr int NCH = IN / KC;         // 128 chunks
constexpr int THREADS = 512;         // 16 warps
constexpr int STAGES  = 4;

constexpr int QS = 68;               // qw smem row stride (ints)  -> bank-shifted rows
constexpr int XS = 72;               // x  smem row stride (halves)
constexpr int WS = 72;               // w  smem row stride (halves)

constexpr int QW_STAGE_I = TO * QS;  // 4352 ints  = 17408 B
constexpr int X_STAGE_H  = TO * XS;  // 4608 halves = 9216 B
constexpr int W_STAGE_H  = TO * WS;  // 4608 halves = 9216 B

constexpr int SMEM_QW_OFF  = 0;
constexpr int SMEM_X_OFF   = STAGES * QW_STAGE_I * 4;              // 69632
constexpr int SMEM_W_OFF   = SMEM_X_OFF + STAGES * X_STAGE_H * 2;  // 106496
constexpr int SMEM_LUT_OFF = SMEM_W_OFF + 2 * W_STAGE_H * 2;       // 124928
constexpr int SMEM_TOTAL   = SMEM_LUT_OFF + TO * 16 * 2;           // 126976 B

__device__ int    g_is_f32;                 // dtype flag (probe)
__device__ __half g_x16[BATCH * IN];        // x pre-converted to fp16

__device__ __forceinline__ void cp_async16(void* smem_dst, const void* gmem_src) {
    unsigned s = (unsigned)__cvta_generic_to_shared(smem_dst);
    asm volatile("cp.async.cg.shared.global [%0], [%1], 16;\n" :: "r"(s), "l"(gmem_src));
}
__device__ __forceinline__ void cp_commit() {
    asm volatile("cp.async.commit_group;\n" ::: "memory");
}
template <int N>
__device__ __forceinline__ void cp_wait() {
    asm volatile("cp.async.wait_group %0;\n" :: "n"(N) : "memory");
}

__device__ __forceinline__ void ldsm_x4(unsigned& r0, unsigned& r1, unsigned& r2, unsigned& r3,
                                        unsigned addr) {
    asm volatile("ldmatrix.sync.aligned.m8n8.x4.shared.b16 {%0,%1,%2,%3}, [%4];\n"
                 : "=r"(r0), "=r"(r1), "=r"(r2), "=r"(r3) : "r"(addr));
}

__device__ __forceinline__ void mma_m16n8k16(float& c0, float& c1, float& c2, float& c3,
                                             unsigned a0, unsigned a1, unsigned a2, unsigned a3,
                                             unsigned b0, unsigned b1) {
    asm volatile(
        "mma.sync.aligned.m16n8k16.row.col.f32.f16.f16.f32 "
        "{%0,%1,%2,%3}, {%4,%5,%6,%7}, {%8,%9}, {%0,%1,%2,%3};\n"
        : "+f"(c0), "+f"(c1), "+f"(c2), "+f"(c3)
        : "r"(a0), "r"(a1), "r"(a2), "r"(a3), "r"(b0), "r"(b1));
}

// ---------------------------------------------------------------------------
// Probe: was the fp16 reference data stored as f32 or f16?  (see round-2 notes)
// ---------------------------------------------------------------------------
__global__ void probe_kernel(const unsigned* __restrict__ lut_words) {
    if (threadIdx.x == 0) {
        int c = 0;
#pragma unroll 1
        for (int i = 0; i < 64; i++) {
            float a = fabsf(__uint_as_float(lut_words[i]));
            if (a > 1e-4f && a < 1.0f) c++;
        }
        g_is_f32 = (c >= 32) ? 1 : 0;
    }
}

// x -> fp16 scratch (one-time per launch, ~2us)
__global__ void xconv_kernel(const void* __restrict__ xp) {
    int i = (blockIdx.x * blockDim.x + threadIdx.x) * 4;
    if (g_is_f32) {
        float4 v = *reinterpret_cast<const float4*>(reinterpret_cast<const float*>(xp) + i);
        __half2 lo = __floats2half2_rn(v.x, v.y);
        __half2 hi = __floats2half2_rn(v.z, v.w);
        *reinterpret_cast<__half2*>(g_x16 + i)     = lo;
        *reinterpret_cast<__half2*>(g_x16 + i + 2) = hi;
    } else {
        *reinterpret_cast<uint2*>(g_x16 + i) =
            *reinterpret_cast<const uint2*>(reinterpret_cast<const __half*>(xp) + i);
    }
}

template <bool F32>
__device__ __forceinline__ void run_impl(const int*  __restrict__ qw,
                                         const void* __restrict__ lutp,
                                         void*       __restrict__ outp,
                                         char* smem) {
    int*    qw_s  = reinterpret_cast<int*>(smem + SMEM_QW_OFF);
    __half* x_s   = reinterpret_cast<__half*>(smem + SMEM_X_OFF);
    __half* w_s   = reinterpret_cast<__half*>(smem + SMEM_W_OFF);
    __half* lut_s = reinterpret_cast<__half*>(smem + SMEM_LUT_OFF);

    const int tid  = threadIdx.x;
    const int lane = tid & 31;
    const int wid  = tid >> 5;
    const int rblk = blockIdx.x * TO;

    // ---- LUT rows for this CTA (as half) ----
    if (F32) {
        const float* lf = reinterpret_cast<const float*>(lutp);
        for (int i = tid; i < TO * 16; i += THREADS)
            lut_s[i] = __float2half_rn(lf[(size_t)rblk * 16 + i]);
    } else {
        const __half* lh = reinterpret_cast<const __half*>(lutp);
        for (int i = tid; i < TO * 16; i += THREADS)
            lut_s[i] = lh[(size_t)rblk * 16 + i];
    }
    __syncthreads();

    // ---- prefetch mapping: thread -> (row, seg) ----
    const int pr = tid >> 3;   // row 0..63
    const int pseg = tid & 7;  // segment 0..7

    auto prefetch = [&](int c) {
        const int buf = c & (STAGES - 1);
        const int k0  = c * KC;
        // x: 64 rows x 128B, 1x16B per thread
        cp_async16(x_s + buf * X_STAGE_H + pr * XS + pseg * 8,
                   g_x16 + (size_t)pr * IN + k0 + pseg * 8);
        // qw: 64 rows x 256B, 2x16B per thread
        const int* qg = qw + (size_t)(rblk + pr) * IN + k0;
        int* qd = qw_s + buf * QW_STAGE_I + pr * QS;
        cp_async16(qd + pseg * 4,       qg + pseg * 4);
        cp_async16(qd + (pseg + 8) * 4, qg + (pseg + 8) * 4);
    };

    prefetch(0); cp_commit();
    prefetch(1); cp_commit();
    prefetch(2); cp_commit();

    // ---- warp decomposition: 2m x 2n x 4k ----
    const int mi = wid >> 3;          // 0..1
    const int ni = (wid >> 2) & 1;    // 0..1
    const int ki = wid & 3;           // 0..3
    const int m_base = mi * 32;
    const int n_base = ni * 32;
    const int k_base = ki * 16;

    const int q = lane >> 3;          // ldmatrix quarter
    const int r = lane & 7;
    const int g = lane >> 2;          // mma accum mapping
    const int t = lane & 3;

    // per-lane ldmatrix byte offsets (constant across chunks)
    unsigned a_off[2], b_off[2];
#pragma unroll
    for (int mt = 0; mt < 2; mt++)
        a_off[mt] = ((m_base + mt * 16 + ((q & 1) << 3) + r) * XS
                     + k_base + ((q >> 1) << 3)) * 2;
#pragma unroll
    for (int nt = 0; nt < 2; nt++)
        b_off[nt] = ((n_base + nt * 16 + ((q >> 1) << 3) + r) * WS
                     + k_base + ((q & 1) << 3)) * 2;

    const unsigned x_base_u = (unsigned)__cvta_generic_to_shared(x_s);
    const unsigned w_base_u = (unsigned)__cvta_generic_to_shared(w_s);

    // dequant mapping: warp owns 4 rows; lane -> (row, seg)
    const int drow = wid * 4 + (lane >> 3);
    const int dseg = lane & 7;
    const __half* lrow = lut_s + drow * 16;

    float acc[2][4][4];
#pragma unroll
    for (int mt = 0; mt < 2; mt++)
#pragma unroll
        for (int j = 0; j < 4; j++)
#pragma unroll
            for (int e = 0; e < 4; e++) acc[mt][j][e] = 0.0f;

    for (int c = 0; c < NCH; c++) {
        const int buf = c & (STAGES - 1);

        // wait for stage c (tail drains pipeline)
        if (c + 3 < NCH)        cp_wait<2>();
        else if (c == NCH - 3)  cp_wait<2>();
        else if (c == NCH - 2)  cp_wait<1>();
        else                    cp_wait<0>();
        __syncthreads();

        // ---- dequant: 2x LDS.128 + 8 gathers + 1x STS.128 per lane ----
        {
            const int* qrow = qw_s + buf * QW_STAGE_I + drow * QS + dseg * 8;
            int4 qa = *reinterpret_cast<const int4*>(qrow);
            int4 qb = *reinterpret_cast<const int4*>(qrow + 4);
            __half2 h01 = __halves2half2(lrow[qa.x & 15], lrow[qa.y & 15]);
            __half2 h23 = __halves2half2(lrow[qa.z & 15], lrow[qa.w & 15]);
            __half2 h45 = __halves2half2(lrow[qb.x & 15], lrow[qb.y & 15]);
            __half2 h67 = __halves2half2(lrow[qb.z & 15], lrow[qb.w & 15]);
            uint4 o;
            o.x = *reinterpret_cast<unsigned*>(&h01);
            o.y = *reinterpret_cast<unsigned*>(&h23);
            o.z = *reinterpret_cast<unsigned*>(&h45);
            o.w = *reinterpret_cast<unsigned*>(&h67);
            *reinterpret_cast<uint4*>(w_s + (c & 1) * W_STAGE_H + drow * WS + dseg * 8) = o;
        }
        __syncthreads();

        // prefetch next stage (after barrier: stage (c-1)%4 fully consumed)
        if (c + 3 < NCH) { prefetch(c + 3); cp_commit(); }

        // ---- mma: 4 ldmatrix.x4 + 8 mma ----
        const unsigned xa = x_base_u + buf * (X_STAGE_H * 2);
        const unsigned wa = w_base_u + (c & 1) * (W_STAGE_H * 2);
        unsigned af[2][4], bf[2][4];
#pragma unroll
        for (int mt = 0; mt < 2; mt++)
            ldsm_x4(af[mt][0], af[mt][1], af[mt][2], af[mt][3], xa + a_off[mt]);
#pragma unroll
        for (int nt = 0; nt < 2; nt++)
            ldsm_x4(bf[nt][0], bf[nt][1], bf[nt][2], bf[nt][3], wa + b_off[nt]);
#pragma unroll
        for (int mt = 0; mt < 2; mt++)
#pragma unroll
            for (int j = 0; j < 4; j++) {
                const int nt = j >> 1, sub = j & 1;
                mma_m16n8k16(acc[mt][j][0], acc[mt][j][1], acc[mt][j][2], acc[mt][j][3],
                             af[mt][0], af[mt][1], af[mt][2], af[mt][3],
                             bf[nt][sub * 2], bf[nt][sub * 2 + 1]);
            }
    }

    // ---- epilogue: k-split reduction via smem (reuses qw stage area) ----
    __syncthreads();
    float* psum = reinterpret_cast<float*>(smem);   // [4][64][64] f32 = 64KB
#pragma unroll
    for (int mt = 0; mt < 2; mt++)
#pragma unroll
        for (int j = 0; j < 4; j++) {
            const int m = m_base + mt * 16 + g;
            const int n = n_base + j * 8 + t * 2;
            *reinterpret_cast<float2*>(psum + ki * 4096 + m * 64 + n) =
                make_float2(acc[mt][j][0], acc[mt][j][1]);
            *reinterpret_cast<float2*>(psum + ki * 4096 + (m + 8) * 64 + n) =
                make_float2(acc[mt][j][2], acc[mt][j][3]);
        }
    __syncthreads();

    {
        const int base = tid * 8;          // 512 threads x 8 outputs = 64x64
        const int m = base >> 6;
        const int n0 = base & 63;
#pragma unroll
        for (int e = 0; e < 8; e++) {
            const int n = n0 + e;
            float s = psum[m * 64 + n] + psum[4096 + m * 64 + n]
                    + psum[8192 + m * 64 + n] + psum[12288 + m * 64 + n];
            if (F32) {
                reinterpret_cast<float*>(outp)[(size_t)m * OUT + rblk + n] =
                    __half2float(__float2half_rn(s));
            } else {
                reinterpret_cast<__half*>(outp)[(size_t)m * OUT + rblk + n] =
                    __float2half_rn(s);
            }
        }
    }
}

__global__ __launch_bounds__(THREADS, 1)
void anyprec_linear_kernel(const int*  __restrict__ qw,
                           const void* __restrict__ lut,
                           void*       __restrict__ out) {
    extern __shared__ char smem[];
    if (g_is_f32) run_impl<true>(qw, lut, out, smem);
    else          run_impl<false>(qw, lut, out, smem);
}

extern "C" void kernel_launch(void* const* d_in, const int* in_sizes, int n_in,
                              void* d_out, int out_size) {
    // Identify inputs by element count:
    //   x: 524288, qweight: 67108864, lut: 131072
    const void* x = nullptr; const int* qw = nullptr; const void* lut = nullptr;
    for (int i = 0; i < n_in; i++) {
        if (in_sizes[i] == BATCH * IN)     x   = d_in[i];
        else if (in_sizes[i] == OUT * IN)  qw  = (const int*)d_in[i];
        else if (in_sizes[i] == OUT * 16)  lut = d_in[i];
    }

    cudaFuncSetAttribute(anyprec_linear_kernel,
                         cudaFuncAttributeMaxDynamicSharedMemorySize, SMEM_TOTAL);

    probe_kernel<<<1, 32>>>(reinterpret_cast<const unsigned*>(lut));
    xconv_kernel<<<BATCH * IN / 4 / 256, 256>>>(x);
    anyprec_linear_kernel<<<OUT / TO, THREADS, SMEM_TOTAL>>>(qw, lut, d_out);
}

// round 7
// speedup vs baseline: 2.2128x; 1.3573x over previous
#include <cuda_runtime.h>
#include <cuda_fp16.h>
#include <cstdint>

// Problem constants
constexpr int BATCH = 64;
constexpr int IN    = 8192;
constexpr int OUT   = 8192;

// Tiling: CTA = 64 out rows x full K, grid 128.
constexpr int TO      = 64;
constexpr int KC      = 64;
constexpr int NCH     = IN / KC;     // 128
constexpr int THREADS = 512;         // 16 warps: 2m x 2n x 4k

constexpr int XS = 72;               // x smem stride (halves) - conflict-free ldsm
constexpr int WS = 72;               // w smem stride (halves)

constexpr int X_STAGE_B = TO * XS * 2;            // 9216 B
constexpr int W_BUF_B   = TO * WS * 2;            // 9216 B
constexpr int X_STAGES  = 4;

constexpr int SMEM_X_OFF   = 0;
constexpr int SMEM_W_OFF   = X_STAGES * X_STAGE_B;    // 36864
// epilogue psum [4][64][64] f32 = 65536 overlays x/w; lut+flag live above it
constexpr int SMEM_LUT_OFF  = 65536;
constexpr int SMEM_FLAG_OFF = SMEM_LUT_OFF + TO * 16 * 2;  // 67584
constexpr int SMEM_TOTAL    = 67840;

__device__ __half g_x16[BATCH * IN];   // x as fp16

__device__ __forceinline__ void cp_async16(unsigned smem_dst, const void* gmem_src) {
    asm volatile("cp.async.cg.shared.global [%0], [%1], 16;\n" :: "r"(smem_dst), "l"(gmem_src));
}
__device__ __forceinline__ void cp_commit() {
    asm volatile("cp.async.commit_group;\n" ::: "memory");
}
template <int N>
__device__ __forceinline__ void cp_wait() {
    asm volatile("cp.async.wait_group %0;\n" :: "n"(N) : "memory");
}
__device__ __forceinline__ void ldsm_x4(unsigned& r0, unsigned& r1, unsigned& r2, unsigned& r3,
                                        unsigned addr) {
    asm volatile("ldmatrix.sync.aligned.m8n8.x4.shared.b16 {%0,%1,%2,%3}, [%4];\n"
                 : "=r"(r0), "=r"(r1), "=r"(r2), "=r"(r3) : "r"(addr));
}
__device__ __forceinline__ void mma_m16n8k16(float& c0, float& c1, float& c2, float& c3,
                                             unsigned a0, unsigned a1, unsigned a2, unsigned a3,
                                             unsigned b0, unsigned b1) {
    asm volatile(
        "mma.sync.aligned.m16n8k16.row.col.f32.f16.f16.f32 "
        "{%0,%1,%2,%3}, {%4,%5,%6,%7}, {%8,%9}, {%0,%1,%2,%3};\n"
        : "+f"(c0), "+f"(c1), "+f"(c2), "+f"(c3)
        : "r"(a0), "r"(a1), "r"(a2), "r"(a3), "r"(b0), "r"(b1));
}

// probe: lut words as f32 land in (1e-4,1) for N(0,0.05) f32 storage; as packed
// half pairs the f32 reinterpretation is < ~3e-5. Ballot over 32 words.
__device__ __forceinline__ int probe_f32(const unsigned* lut_words, int lane) {
    float a = fabsf(__uint_as_float(lut_words[lane]));
    unsigned m = __ballot_sync(0xffffffffu, a > 1e-4f && a < 1.0f);
    return __popc(m) >= 16;
}

// ---- launch 1: x -> fp16 scratch (probe inline, per block) ----
__global__ void xconv_kernel(const void* __restrict__ xp,
                             const unsigned* __restrict__ lut_words) {
    __shared__ int flag_s;
    const int tid = threadIdx.x;
    if (tid < 32) {
        int f = probe_f32(lut_words, tid);
        if (tid == 0) flag_s = f;
    }
    __syncthreads();
    const int i = (blockIdx.x * blockDim.x + tid) * 4;
    if (flag_s) {
        float4 v = *reinterpret_cast<const float4*>(reinterpret_cast<const float*>(xp) + i);
        *reinterpret_cast<__half2*>(g_x16 + i)     = __floats2half2_rn(v.x, v.y);
        *reinterpret_cast<__half2*>(g_x16 + i + 2) = __floats2half2_rn(v.z, v.w);
    } else {
        *reinterpret_cast<uint2*>(g_x16 + i) =
            *reinterpret_cast<const uint2*>(reinterpret_cast<const __half*>(xp) + i);
    }
}

// ---- launch 2: main ----
__global__ __launch_bounds__(THREADS, 1)
void anyprec_linear_kernel(const int*  __restrict__ qw,
                           const void* __restrict__ lutp,
                           void*       __restrict__ outp) {
    extern __shared__ char smem[];
    __half* lut_s  = reinterpret_cast<__half*>(smem + SMEM_LUT_OFF);
    int*    flag_p = reinterpret_cast<int*>(smem + SMEM_FLAG_OFF);
    const unsigned smem_u = (unsigned)__cvta_generic_to_shared(smem);
    const unsigned x_u    = smem_u + SMEM_X_OFF;
    const unsigned w_u    = smem_u + SMEM_W_OFF;

    const int tid  = threadIdx.x;
    const int lane = tid & 31;
    const int wid  = tid >> 5;
    const int rblk = blockIdx.x * TO;

    if (tid < 32) {
        int f = probe_f32(reinterpret_cast<const unsigned*>(lutp), lane);
        if (lane == 0) *flag_p = f;
    }
    __syncthreads();
    const bool F32 = (*flag_p != 0);

    // LUT rows -> smem (as half)
    if (F32) {
        const float* lf = reinterpret_cast<const float*>(lutp);
        for (int i = tid; i < TO * 16; i += THREADS)
            lut_s[i] = __float2half_rn(lf[(size_t)rblk * 16 + i]);
    } else {
        const __half* lh = reinterpret_cast<const __half*>(lutp);
        for (int i = tid; i < TO * 16; i += THREADS)
            lut_s[i] = lh[(size_t)rblk * 16 + i];
    }

    // ---- x prefetch mapping: thread -> (row 0..63, 16B seg 0..7) ----
    const int xr = tid >> 3, x8 = tid & 7;
    const __half* xg_base = g_x16 + (size_t)xr * IN + x8 * 8;
    const unsigned x_dst  = x_u + (xr * XS + x8 * 8) * 2;

    auto xfetch = [&](int c) {
        cp_async16(x_dst + (c & 3) * X_STAGE_B, xg_base + c * KC);
    };

    // ---- qw LDG mapping: thread -> (row 0..63, 8-int seg 0..7) ----
    const int drow = tid >> 3, dseg = tid & 7;
    const int4* qptr = reinterpret_cast<const int4*>(
        qw + (size_t)(rblk + drow) * IN + dseg * 8);   // +c*16 per chunk
    const __half* lrow = lut_s + drow * 16;
    const unsigned w_st = w_u + (drow * WS + dseg * 8) * 2;

    xfetch(0); cp_commit();
    xfetch(1); cp_commit();
    xfetch(2); cp_commit();

    int4 qq0[4], qq1[4];
    qq0[0] = __ldcs(qptr);      qq1[0] = __ldcs(qptr + 1);
    qq0[1] = __ldcs(qptr + 16); qq1[1] = __ldcs(qptr + 17);

    // ---- warp decomposition: 2m x 2n x 4k ----
    const int mi = wid >> 3, ni = (wid >> 2) & 1, ki = wid & 3;
    const int m_base = mi * 32, n_base = ni * 32, k_base = ki * 16;
    const int q = lane >> 3, r = lane & 7, g = lane >> 2, t = lane & 3;

    unsigned a_off[2], b_off[2];
#pragma unroll
    for (int mt = 0; mt < 2; mt++)
        a_off[mt] = ((m_base + mt * 16 + ((q & 1) << 3) + r) * XS
                     + k_base + ((q >> 1) << 3)) * 2;
#pragma unroll
    for (int nt = 0; nt < 2; nt++)
        b_off[nt] = ((n_base + nt * 16 + ((q >> 1) << 3) + r) * WS
                     + k_base + ((q & 1) << 3)) * 2;

    float acc[2][4][4];
#pragma unroll
    for (int mt = 0; mt < 2; mt++)
#pragma unroll
        for (int j = 0; j < 4; j++)
#pragma unroll
            for (int e = 0; e < 4; e++) acc[mt][j][e] = 0.0f;

#pragma unroll 4
    for (int c = 0; c < NCH; c++) {
        // stream qweight 2 chunks ahead (register ring, indices fold via unroll)
        if (c + 2 < NCH) {
            qq0[(c + 2) & 3] = __ldcs(qptr + (c + 2) * 16);
            qq1[(c + 2) & 3] = __ldcs(qptr + (c + 2) * 16 + 1);
        }

        cp_wait<2>();          // x stage c landed (this thread's part)
        __syncthreads();       // all parts visible; iter c-1 ldsm retired

        if (c + 3 < NCH) xfetch(c + 3);
        cp_commit();           // commit every iter keeps wait<2> invariant

        // ---- dequant 8 ints -> 8 halves -> one STS.128 ----
        {
            const int4 qa = qq0[c & 3];
            const int4 qb = qq1[c & 3];
            __half2 h0 = __halves2half2(lrow[qa.x & 15], lrow[qa.y & 15]);
            __half2 h1 = __halves2half2(lrow[qa.z & 15], lrow[qa.w & 15]);
            __half2 h2 = __halves2half2(lrow[qb.x & 15], lrow[qb.y & 15]);
            __half2 h3 = __halves2half2(lrow[qb.z & 15], lrow[qb.w & 15]);
            asm volatile("st.shared.v4.b32 [%0], {%1,%2,%3,%4};" ::
                         "r"(w_st + (c & 1) * W_BUF_B),
                         "r"(*reinterpret_cast<unsigned*>(&h0)),
                         "r"(*reinterpret_cast<unsigned*>(&h1)),
                         "r"(*reinterpret_cast<unsigned*>(&h2)),
                         "r"(*reinterpret_cast<unsigned*>(&h3)) : "memory");
        }
        __syncthreads();       // w tile visible

        // ---- mma: 4 ldmatrix.x4 + 8 mma ----
        const unsigned xa = x_u + (c & 3) * X_STAGE_B;
        const unsigned wa = w_u + (c & 1) * W_BUF_B;
        unsigned af[2][4], bf[2][4];
#pragma unroll
        for (int mt = 0; mt < 2; mt++)
            ldsm_x4(af[mt][0], af[mt][1], af[mt][2], af[mt][3], xa + a_off[mt]);
#pragma unroll
        for (int nt = 0; nt < 2; nt++)
            ldsm_x4(bf[nt][0], bf[nt][1], bf[nt][2], bf[nt][3], wa + b_off[nt]);
#pragma unroll
        for (int mt = 0; mt < 2; mt++)
#pragma unroll
            for (int j = 0; j < 4; j++) {
                const int nt = j >> 1, sub = j & 1;
                mma_m16n8k16(acc[mt][j][0], acc[mt][j][1], acc[mt][j][2], acc[mt][j][3],
                             af[mt][0], af[mt][1], af[mt][2], af[mt][3],
                             bf[nt][sub * 2], bf[nt][sub * 2 + 1]);
            }
    }

    // ---- epilogue: k-split reduction via smem psum (overlays x/w) ----
    __syncthreads();
    float* psum = reinterpret_cast<float*>(smem);   // [4][64][64]
#pragma unroll
    for (int mt = 0; mt < 2; mt++)
#pragma unroll
        for (int j = 0; j < 4; j++) {
            const int m = m_base + mt * 16 + g;
            const int n = n_base + j * 8 + t * 2;
            *reinterpret_cast<float2*>(psum + ki * 4096 + m * 64 + n) =
                make_float2(acc[mt][j][0], acc[mt][j][1]);
            *reinterpret_cast<float2*>(psum + ki * 4096 + (m + 8) * 64 + n) =
                make_float2(acc[mt][j][2], acc[mt][j][3]);
        }
    __syncthreads();

    {
        const int base = tid * 8;          // 512 threads x 8 outputs = 64x64
        const int m = base >> 6;
        const int n0 = base & 63;
#pragma unroll
        for (int e = 0; e < 8; e++) {
            const int n = n0 + e;
            float s = psum[m * 64 + n] + psum[4096 + m * 64 + n]
                    + psum[8192 + m * 64 + n] + psum[12288 + m * 64 + n];
            if (F32) {
                reinterpret_cast<float*>(outp)[(size_t)m * OUT + rblk + n] =
                    __half2float(__float2half_rn(s));
            } else {
                reinterpret_cast<__half*>(outp)[(size_t)m * OUT + rblk + n] =
                    __float2half_rn(s);
            }
        }
    }
}

extern "C" void kernel_launch(void* const* d_in, const int* in_sizes, int n_in,
                              void* d_out, int out_size) {
    // Identify inputs by element count:
    //   x: 524288, qweight: 67108864, lut: 131072
    const void* x = nullptr; const int* qw = nullptr; const void* lut = nullptr;
    for (int i = 0; i < n_in; i++) {
        if (in_sizes[i] == BATCH * IN)     x   = d_in[i];
        else if (in_sizes[i] == OUT * IN)  qw  = (const int*)d_in[i];
        else if (in_sizes[i] == OUT * 16)  lut = d_in[i];
    }

    cudaFuncSetAttribute(anyprec_linear_kernel,
                         cudaFuncAttributeMaxDynamicSharedMemorySize, SMEM_TOTAL);

    xconv_kernel<<<BATCH * IN / 4 / 256, 256>>>(x, reinterpret_cast<const unsigned*>(lut));
    anyprec_linear_kernel<<<OUT / TO, THREADS, SMEM_TOTAL>>>(qw, lut, d_out);
}